// round 2
// baseline (speedup 1.0000x reference)
#include <cuda_runtime.h>
#include <math.h>
#include <stdint.h>

#define DHID 512
#define DOUT 40
#define NMAX 50000
#define NPAD 50048   // multiple of 128

// ---------------- device scratch (allocation-free rule: __device__ globals) ----
__device__ float g_hs [(size_t)NPAD * DHID];   // (A @ W) * dis[row]
__device__ float g_acc[(size_t)NPAD * DHID];   // scatter accumulator / conv out
__device__ float g_x1 [(size_t)NPAD * DHID];
__device__ float g_x2 [(size_t)NPAD * DHID];
__device__ float g_dis[NMAX];                  // deg -> rsqrt(deg)
__device__ float g_colsum[DHID];
__device__ float g_colsq [DHID];

// ---------------- degree / normalization ----------------
__global__ void k_init_deg(int M) {
    int i = blockIdx.x * blockDim.x + threadIdx.x;
    if (i < M) g_dis[i] = 1.0f;                // self-loop contributes 1
}
__global__ void k_deg_scatter(const int* __restrict__ dst, int E) {
    int e = blockIdx.x * blockDim.x + threadIdx.x;
    if (e < E) atomicAdd(&g_dis[dst[e]], 1.0f);
}
__global__ void k_deg_rsqrt(int M) {
    int i = blockIdx.x * blockDim.x + threadIdx.x;
    if (i < M) g_dis[i] = rsqrtf(g_dis[i]);    // deg >= 1 always
}

// ---------------- SGEMM: g_hs[r,:] = (A[r,:] @ W) * dis[r] ----------------
// A selected by selA: 0 = external x, 1 = g_x1, 2 = g_x2.
// 128x128 tile, BK=8, 256 threads, 8x8 per thread (split 4+4).
__global__ void k_sgemm_scale(const float* __restrict__ Aext, int selA,
                              const float* __restrict__ W, int M) {
    const float* A = (selA == 0) ? Aext : (selA == 1) ? g_x1 : g_x2;
    __shared__ float As[8][128];
    __shared__ float Bs[8][128];
    const int tid = threadIdx.x;
    const int bm = blockIdx.y * 128;
    const int bn = blockIdx.x * 128;

    const int arow = tid >> 1;            // 0..127
    const int acol = (tid & 1) * 4;       // 0 or 4
    const int brow = tid >> 5;            // 0..7
    const int bcol = (tid & 31) * 4;      // 0..124

    const int tx4 = (tid & 15) * 4;       // col base within tile
    const int ty4 = (tid >> 4) * 4;       // row base within tile

    float acc[8][8];
#pragma unroll
    for (int i = 0; i < 8; i++)
#pragma unroll
        for (int j = 0; j < 8; j++) acc[i][j] = 0.f;

    for (int k0 = 0; k0 < DHID; k0 += 8) {
        float4 a4 = make_float4(0.f, 0.f, 0.f, 0.f);
        int gr = bm + arow;
        if (gr < M) a4 = *(const float4*)(A + (size_t)gr * DHID + k0 + acol);
        As[acol + 0][arow] = a4.x;
        As[acol + 1][arow] = a4.y;
        As[acol + 2][arow] = a4.z;
        As[acol + 3][arow] = a4.w;
        *(float4*)&Bs[brow][bcol] =
            *(const float4*)(W + (size_t)(k0 + brow) * DHID + bn + bcol);
        __syncthreads();

#pragma unroll
        for (int k = 0; k < 8; k++) {
            float4 a0 = *(const float4*)&As[k][ty4];
            float4 a1 = *(const float4*)&As[k][ty4 + 64];
            float4 b0 = *(const float4*)&Bs[k][tx4];
            float4 b1 = *(const float4*)&Bs[k][tx4 + 64];
            float af[8]  = {a0.x, a0.y, a0.z, a0.w, a1.x, a1.y, a1.z, a1.w};
            float bfr[8] = {b0.x, b0.y, b0.z, b0.w, b1.x, b1.y, b1.z, b1.w};
#pragma unroll
            for (int i = 0; i < 8; i++)
#pragma unroll
                for (int j = 0; j < 8; j++) acc[i][j] += af[i] * bfr[j];
        }
        __syncthreads();
    }

#pragma unroll
    for (int i = 0; i < 8; i++) {
        int gr = bm + ((i < 4) ? (ty4 + i) : (64 + ty4 + i - 4));
        if (gr >= M) continue;
        float s = g_dis[gr];
        float4 v0 = make_float4(acc[i][0] * s, acc[i][1] * s, acc[i][2] * s, acc[i][3] * s);
        float4 v1 = make_float4(acc[i][4] * s, acc[i][5] * s, acc[i][6] * s, acc[i][7] * s);
        *(float4*)(g_hs + (size_t)gr * DHID + bn + tx4)      = v0;
        *(float4*)(g_hs + (size_t)gr * DHID + bn + 64 + tx4) = v1;
    }
}

// ---------------- zero g_acc + stats ----------------
__global__ void k_zero_acc(int n4) {
    int i = blockIdx.x * blockDim.x + threadIdx.x;
    if (i < n4) ((float4*)g_acc)[i] = make_float4(0.f, 0.f, 0.f, 0.f);
}
__global__ void k_zero_stats() {
    int t = threadIdx.x;
    g_colsum[t] = 0.f;
    g_colsq[t]  = 0.f;
}

// ---------------- edge scatter: g_acc[dst] += g_hs[src] (vector red) ----------
__global__ void k_edge_scatter(const int* __restrict__ src, const int* __restrict__ dst, int E) {
    int idx  = blockIdx.x * blockDim.x + threadIdx.x;
    int e    = idx >> 5;
    int lane = idx & 31;
    if (e >= E) return;
    int s = src[e], d = dst[e];
    const float4* sr = (const float4*)(g_hs + (size_t)s * DHID);
    float* dr = g_acc + (size_t)d * DHID;
#pragma unroll
    for (int i = 0; i < 4; i++) {
        int c = lane + i * 32;            // float4 index 0..127
        float4 v = sr[c];
        asm volatile("red.global.add.v4.f32 [%0], {%1,%2,%3,%4};"
                     :: "l"(dr + c * 4), "f"(v.x), "f"(v.y), "f"(v.z), "f"(v.w)
                     : "memory");
    }
}

// ---------------- fused finalize + BN column stats (layers 1-2) -------------
// g_acc[r,c] = (g_acc[r,c] + g_hs[r,c]) * dis[r]; accumulate col sum / sumsq.
// One thread per column, 128 rows per block; column-adjacent threads coalesce.
__global__ void k_fin_stats(int M) {
    int c  = threadIdx.x;                 // 0..511
    int r0 = blockIdx.x * 128;
    float s = 0.f, q = 0.f;
    int rend = min(r0 + 128, M);
    for (int r = r0; r < rend; r++) {
        size_t off = (size_t)r * DHID + c;
        float v = (g_acc[off] + g_hs[off]) * g_dis[r];
        g_acc[off] = v;
        s += v; q += v * v;
    }
    atomicAdd(&g_colsum[c], s);
    atomicAdd(&g_colsq[c], q);
}

// ---------------- finalize with bias (layer 3, no BN) -----------------------
__global__ void k_finalize_bias(const float* __restrict__ bias, int M) {
    int idx = blockIdx.x * blockDim.x + threadIdx.x;
    int n4 = M * (DHID / 4);
    if (idx >= n4) return;
    int r  = idx >> 7;
    int c4 = idx & 127;
    float4 a = ((const float4*)g_acc)[idx];
    float4 h = ((const float4*)g_hs)[idx];
    float s = g_dis[r];
    float4 b = ((const float4*)bias)[c4];
    ((float4*)g_acc)[idx] = make_float4((a.x + h.x) * s + b.x,
                                        (a.y + h.y) * s + b.y,
                                        (a.z + h.z) * s + b.z,
                                        (a.w + h.w) * s + b.w);
}

// ---------------- BN apply + ReLU -> g_x1 or g_x2 ---------------------------
__global__ void k_bn_apply(const float* __restrict__ gam, const float* __restrict__ bet,
                           int selOut, int M) {
    float* out = (selOut == 1) ? g_x1 : g_x2;
    int idx = blockIdx.x * blockDim.x + threadIdx.x;
    int n4 = M * (DHID / 4);
    if (idx >= n4) return;
    int c4 = idx & 127;
    float invN = 1.0f / (float)M;
    float4 v  = ((const float4*)g_acc)[idx];
    float4 s4 = ((const float4*)g_colsum)[c4];
    float4 q4 = ((const float4*)g_colsq)[c4];
    float4 gm = ((const float4*)gam)[c4];
    float4 bt = ((const float4*)bet)[c4];
    float4 o;
    { float mu = s4.x * invN; float var = q4.x * invN - mu * mu;
      o.x = fmaxf(0.f, (v.x - mu) * rsqrtf(var + 1e-5f) * gm.x + bt.x); }
    { float mu = s4.y * invN; float var = q4.y * invN - mu * mu;
      o.y = fmaxf(0.f, (v.y - mu) * rsqrtf(var + 1e-5f) * gm.y + bt.y); }
    { float mu = s4.z * invN; float var = q4.z * invN - mu * mu;
      o.z = fmaxf(0.f, (v.z - mu) * rsqrtf(var + 1e-5f) * gm.z + bt.z); }
    { float mu = s4.w * invN; float var = q4.w * invN - mu * mu;
      o.w = fmaxf(0.f, (v.w - mu) * rsqrtf(var + 1e-5f) * gm.w + bt.w); }
    ((float4*)out)[idx] = o;
}

// ---------------- JK max + 512->40 classifier + log_softmax -----------------
__global__ void k_jk_head(const float* __restrict__ Wf, const float* __restrict__ bfv,
                          float* __restrict__ out) {
    __shared__ float h[DHID];
    __shared__ float logits[DOUT];
    __shared__ float red2[2];
    int r = blockIdx.x;
    size_t base = (size_t)r * DHID;
    for (int k = threadIdx.x; k < DHID; k += blockDim.x) {
        float v = fmaxf(g_x1[base + k], g_x2[base + k]);
        h[k] = fmaxf(v, g_acc[base + k]);      // g_acc holds x3
    }
    __syncthreads();
    int j = threadIdx.x;
    if (j < DOUT) {
        float a = bfv[j];
#pragma unroll 8
        for (int k = 0; k < DHID; k++) a += h[k] * Wf[k * DOUT + j];
        logits[j] = a;
    }
    __syncthreads();
    if (threadIdx.x == 0) {
        float m = -1e30f;
        for (int t = 0; t < DOUT; t++) m = fmaxf(m, logits[t]);
        float s = 0.f;
        for (int t = 0; t < DOUT; t++) s += expf(logits[t] - m);
        red2[0] = m; red2[1] = logf(s);
    }
    __syncthreads();
    if (j < DOUT) out[(size_t)r * DOUT + j] = logits[j] - red2[0] - red2[1];
}

// ---------------- host driver: kernel launches ONLY -------------------------
extern "C" void kernel_launch(void* const* d_in, const int* in_sizes, int n_in,
                              void* d_out, int out_size) {
    const float* x   = (const float*)d_in[0];
    const int*   ei  = (const int*)  d_in[1];
    const float* W1  = (const float*)d_in[2];
    const float* g1  = (const float*)d_in[4];
    const float* be1 = (const float*)d_in[5];
    const float* W2  = (const float*)d_in[6];
    const float* g2  = (const float*)d_in[8];
    const float* be2 = (const float*)d_in[9];
    const float* W3  = (const float*)d_in[10];
    const float* b3  = (const float*)d_in[11];
    const float* Wf  = (const float*)d_in[12];
    const float* bf  = (const float*)d_in[13];
    float* out = (float*)d_out;

    int M = in_sizes[0] / DHID;     // 50000
    int E = in_sizes[1] / 2;        // 800000
    const int* src = ei;
    const int* dst = ei + E;

    int n4 = M * (DHID / 4);
    dim3 gemm_grid(DHID / 128, (M + 127) / 128);
    int statBlocks = (M + 127) / 128;

    // normalization coefficients
    k_init_deg   <<<(M + 255) / 256, 256>>>(M);
    k_deg_scatter<<<(E + 255) / 256, 256>>>(dst, E);
    k_deg_rsqrt  <<<(M + 255) / 256, 256>>>(M);

    // ---- layer 1 ----
    k_sgemm_scale <<<gemm_grid, 256>>>(x, 0, W1, M);
    k_zero_acc    <<<(n4 + 255) / 256, 256>>>(n4);
    k_edge_scatter<<<((size_t)E * 32 + 255) / 256, 256>>>(src, dst, E);
    k_zero_stats  <<<1, DHID>>>();
    k_fin_stats   <<<statBlocks, DHID>>>(M);     // bias cancels under BN
    k_bn_apply    <<<(n4 + 255) / 256, 256>>>(g1, be1, 1, M);

    // ---- layer 2 ----
    k_sgemm_scale <<<gemm_grid, 256>>>(nullptr, 1, W2, M);
    k_zero_acc    <<<(n4 + 255) / 256, 256>>>(n4);
    k_edge_scatter<<<((size_t)E * 32 + 255) / 256, 256>>>(src, dst, E);
    k_zero_stats  <<<1, DHID>>>();
    k_fin_stats   <<<statBlocks, DHID>>>(M);
    k_bn_apply    <<<(n4 + 255) / 256, 256>>>(g2, be2, 2, M);

    // ---- layer 3 (no BN, keep bias; x3 stays in g_acc) ----
    k_sgemm_scale <<<gemm_grid, 256>>>(nullptr, 2, W3, M);
    k_zero_acc    <<<(n4 + 255) / 256, 256>>>(n4);
    k_edge_scatter<<<((size_t)E * 32 + 255) / 256, 256>>>(src, dst, E);
    k_finalize_bias<<<(n4 + 255) / 256, 256>>>(b3, M);

    // ---- JK max + classifier + log_softmax ----
    k_jk_head<<<M, 64>>>(Wf, bf, out);
}

// round 5
// speedup vs baseline: 1.2845x; 1.2845x over previous
#include <cuda_runtime.h>
#include <cuda_bf16.h>
#include <math.h>
#include <stdint.h>

#define DHID 512
#define DOUT 40
#define NMAX 50000
#define NPAD 50048

// ---------------- device scratch ----------------
__device__ float g_hs [(size_t)NPAD * DHID];   // conv pre-scatter: (A@W)*dis
__device__ float g_acc[(size_t)NPAD * DHID];   // scatter accumulator / conv out
__device__ float g_x1 [(size_t)NPAD * DHID];
__device__ float g_x2 [(size_t)NPAD * DHID];
__device__ float g_dis[NMAX];
__device__ float g_colsum[DHID];
__device__ float g_colsq [DHID];
__device__ __nv_bfloat16 g_Ahi[(size_t)NPAD * DHID];
__device__ __nv_bfloat16 g_Alo[(size_t)NPAD * DHID];
__device__ __nv_bfloat16 g_Wthi[3 * DHID * DHID];  // W^T split-hi, [layer][n][k]
__device__ __nv_bfloat16 g_Wtlo[3 * DHID * DHID];

// ================= helpers =================
__device__ __forceinline__ uint32_t smem_u32(const void* p) {
    uint32_t a;
    asm("{ .reg .u64 t; cvta.to.shared.u64 t, %1; cvt.u32.u64 %0, t; }" : "=r"(a) : "l"(p));
    return a;
}
#define CP_ASYNC16(dst, src) \
    asm volatile("cp.async.cg.shared.global [%0], [%1], 16;" :: "r"(dst), "l"(src))
#define CP_COMMIT() asm volatile("cp.async.commit_group;" ::: "memory")
#define LDMATRIX_X4(r0, r1, r2, r3, addr) \
    asm volatile("ldmatrix.sync.aligned.m8n8.x4.shared.b16 {%0,%1,%2,%3}, [%4];" \
                 : "=r"(r0), "=r"(r1), "=r"(r2), "=r"(r3) : "r"(addr))
#define MMA16816(c0, c1, c2, c3, a0, a1, a2, a3, b0, b1) \
    asm volatile("mma.sync.aligned.m16n8k16.row.col.f32.bf16.bf16.f32 " \
                 "{%0,%1,%2,%3}, {%4,%5,%6,%7}, {%8,%9}, {%0,%1,%2,%3};" \
                 : "+f"(c0), "+f"(c1), "+f"(c2), "+f"(c3) \
                 : "r"(a0), "r"(a1), "r"(a2), "r"(a3), "r"(b0), "r"(b1))

// ================= degree / normalization =================
__global__ void k_init_deg(int M) {
    int i = blockIdx.x * blockDim.x + threadIdx.x;
    if (i < M) g_dis[i] = 1.0f;
}
__global__ void k_deg_scatter(const int* __restrict__ dst, int E) {
    int e = blockIdx.x * blockDim.x + threadIdx.x;
    if (e < E) atomicAdd(&g_dis[dst[e]], 1.0f);
}
__global__ void k_deg_rsqrt(int M) {
    int i = blockIdx.x * blockDim.x + threadIdx.x;
    if (i < M) g_dis[i] = rsqrtf(g_dis[i]);
}

// ================= weight transpose + bf16 split =================
__global__ void k_convert_W(const float* __restrict__ W1, const float* __restrict__ W2,
                            const float* __restrict__ W3) {
    __shared__ float tile[32][33];
    int w = blockIdx.z;
    const float* W = (w == 0) ? W1 : (w == 1) ? W2 : W3;
    int k = blockIdx.y * 32 + threadIdx.y;
    int n = blockIdx.x * 32 + threadIdx.x;
    tile[threadIdx.y][threadIdx.x] = W[k * DHID + n];
    __syncthreads();
    int n2 = blockIdx.x * 32 + threadIdx.y;
    int k2 = blockIdx.y * 32 + threadIdx.x;
    float v = tile[threadIdx.x][threadIdx.y];
    __nv_bfloat16 hi = __float2bfloat16_rn(v);
    __nv_bfloat16 lo = __float2bfloat16_rn(v - __bfloat162float(hi));
    size_t off = (size_t)w * DHID * DHID + (size_t)n2 * DHID + k2;
    g_Wthi[off] = hi;
    g_Wtlo[off] = lo;
}

// ================= x -> bf16 hi/lo =================
__global__ void k_convert_x(const float* __restrict__ x, int M) {
    int idx = blockIdx.x * blockDim.x + threadIdx.x;
    int n4 = M * (DHID / 4);
    if (idx >= n4) return;
    float4 v = ((const float4*)x)[idx];
    float hx = __bfloat162float(__float2bfloat16_rn(v.x));
    float hy = __bfloat162float(__float2bfloat16_rn(v.y));
    float hz = __bfloat162float(__float2bfloat16_rn(v.z));
    float hw = __bfloat162float(__float2bfloat16_rn(v.w));
    ((__nv_bfloat162*)g_Ahi)[idx * 2    ] = __floats2bfloat162_rn(v.x, v.y);
    ((__nv_bfloat162*)g_Ahi)[idx * 2 + 1] = __floats2bfloat162_rn(v.z, v.w);
    ((__nv_bfloat162*)g_Alo)[idx * 2    ] = __floats2bfloat162_rn(v.x - hx, v.y - hy);
    ((__nv_bfloat162*)g_Alo)[idx * 2 + 1] = __floats2bfloat162_rn(v.z - hz, v.w - hw);
}

// ================= split-bf16 GEMM via mma.sync =================
// g_hs[128 x 512 tile] = (A @ W^T) * dis, virtual K' = 1536:
// it 0-15: Ahi*Bhi, 16-31: Alo*Bhi, 32-47: Ahi*Blo.
#define BK 32
#define NIT 48
#define RSB 80                    // smem row stride bytes (64B data + 16B pad)
#define TILE_B (128 * RSB)        // 10240 B per tile

static __device__ __forceinline__ void load_tile(uint32_t sA, uint32_t sB, int it,
                                                 int bm, int bn, int M, int layer, int tid) {
    int sel = it >> 4;
    int k0  = (it & 15) * BK;
    const __nv_bfloat16* Asrc = (sel == 1) ? g_Alo : g_Ahi;
    const __nv_bfloat16* Bsrc = ((sel == 2) ? g_Wtlo : g_Wthi) + (size_t)layer * DHID * DHID;
#pragma unroll
    for (int j = 0; j < 2; j++) {
        int chunk = tid + 256 * j;       // 0..511
        int row = chunk >> 2;            // 0..127
        int c16 = chunk & 3;
        int gr = min(bm + row, M - 1);
        CP_ASYNC16(sA + row * RSB + c16 * 16,
                   (const char*)(Asrc + (size_t)gr * DHID + k0 + c16 * 8));
        CP_ASYNC16(sB + row * RSB + c16 * 16,
                   (const char*)(Bsrc + (size_t)(bn + row) * DHID + k0 + c16 * 8));
    }
}

__global__ void __launch_bounds__(256) k_gemm_mma(int layer, int M) {
    __shared__ __align__(16) char smem[2 * 2 * TILE_B];   // [stage][A/B]
    const uint32_t sb = smem_u32(smem);
    const int tid  = threadIdx.x;
    const int wid  = tid >> 5;
    const int lane = tid & 31;
    const int wm = wid >> 1;          // 0..3  (rows, 32 each)
    const int wn = wid & 1;           // 0..1  (cols, 64 each)
    const int bm = blockIdx.y * 128;
    const int bn = blockIdx.x * 128;

    float c[2][8][4];
#pragma unroll
    for (int i = 0; i < 2; i++)
#pragma unroll
        for (int j = 0; j < 8; j++)
#pragma unroll
            for (int q = 0; q < 4; q++) c[i][j][q] = 0.f;

    // ldmatrix smem addresses
    const uint32_t aRow = wm * 32 + (lane & 15);
    const uint32_t aCol = (lane >> 4) * 8;
    const uint32_t bRow = wn * 64 + (lane & 7) + ((lane >> 4) << 3);
    const uint32_t bCol = ((lane >> 3) & 1) * 8;

    load_tile(sb, sb + TILE_B, 0, bm, bn, M, layer, tid);
    CP_COMMIT();

    for (int it = 0; it < NIT; it++) {
        if (it + 1 < NIT) {
            uint32_t so = ((it + 1) & 1) * (2 * TILE_B);
            load_tile(sb + so, sb + so + TILE_B, it + 1, bm, bn, M, layer, tid);
            CP_COMMIT();
            asm volatile("cp.async.wait_group 1;" ::: "memory");
        } else {
            asm volatile("cp.async.wait_group 0;" ::: "memory");
        }
        __syncthreads();

        uint32_t so = (it & 1) * (2 * TILE_B);
        uint32_t sA = sb + so, sB = sb + so + TILE_B;
#pragma unroll
        for (int kk = 0; kk < 2; kk++) {
            uint32_t a0[4], a1[4];
            LDMATRIX_X4(a0[0], a0[1], a0[2], a0[3],
                        sA + aRow * RSB + (kk * 16 + aCol) * 2);
            LDMATRIX_X4(a1[0], a1[1], a1[2], a1[3],
                        sA + (aRow + 16) * RSB + (kk * 16 + aCol) * 2);
            uint32_t b[8][2];
#pragma unroll
            for (int nb = 0; nb < 4; nb++) {
                uint32_t r0, r1, r2, r3;
                LDMATRIX_X4(r0, r1, r2, r3,
                            sB + (bRow + nb * 16) * RSB + (kk * 16 + bCol) * 2);
                b[nb * 2 + 0][0] = r0; b[nb * 2 + 0][1] = r1;
                b[nb * 2 + 1][0] = r2; b[nb * 2 + 1][1] = r3;
            }
#pragma unroll
            for (int ni = 0; ni < 8; ni++) {
                MMA16816(c[0][ni][0], c[0][ni][1], c[0][ni][2], c[0][ni][3],
                         a0[0], a0[1], a0[2], a0[3], b[ni][0], b[ni][1]);
                MMA16816(c[1][ni][0], c[1][ni][1], c[1][ni][2], c[1][ni][3],
                         a1[0], a1[1], a1[2], a1[3], b[ni][0], b[ni][1]);
            }
        }
        __syncthreads();
    }

    // epilogue: scale by dis[row], store float2
    int colBase = bn + wn * 64 + (lane & 3) * 2;
#pragma unroll
    for (int mi = 0; mi < 2; mi++) {
        int r0 = bm + wm * 32 + mi * 16 + (lane >> 2);
#pragma unroll
        for (int half = 0; half < 2; half++) {
            int r = r0 + half * 8;
            if (r >= M) continue;
            float s = g_dis[r];
            float* dstrow = g_hs + (size_t)r * DHID;
#pragma unroll
            for (int ni = 0; ni < 8; ni++) {
                float2 v = make_float2(c[mi][ni][half * 2 + 0] * s,
                                       c[mi][ni][half * 2 + 1] * s);
                *(float2*)(dstrow + colBase + ni * 8) = v;
            }
        }
    }
}

// ================= zero helpers =================
__global__ void k_zero_acc(int n4) {
    int i = blockIdx.x * blockDim.x + threadIdx.x;
    if (i < n4) ((float4*)g_acc)[i] = make_float4(0.f, 0.f, 0.f, 0.f);
}
__global__ void k_zero_stats() {
    int t = threadIdx.x;
    g_colsum[t] = 0.f;
    g_colsq[t]  = 0.f;
}

// ================= edge scatter: g_acc[dst] += g_hs[src] =================
__global__ void k_edge_scatter(const int* __restrict__ src, const int* __restrict__ dst, int E) {
    int idx  = blockIdx.x * blockDim.x + threadIdx.x;
    int e    = idx >> 5;
    int lane = idx & 31;
    if (e >= E) return;
    int s = src[e], d = dst[e];
    const float4* sr = (const float4*)(g_hs + (size_t)s * DHID);
    float* dr = g_acc + (size_t)d * DHID;
#pragma unroll
    for (int i = 0; i < 4; i++) {
        int c = lane + i * 32;
        float4 v = sr[c];
        asm volatile("red.global.add.v4.f32 [%0], {%1,%2,%3,%4};"
                     :: "l"(dr + c * 4), "f"(v.x), "f"(v.y), "f"(v.z), "f"(v.w)
                     : "memory");
    }
}

// ================= fused finalize + BN column stats =================
__global__ void k_fin_stats(int M) {
    int c  = threadIdx.x;
    int r0 = blockIdx.x * 128;
    float s = 0.f, q = 0.f;
    int rend = min(r0 + 128, M);
    for (int r = r0; r < rend; r++) {
        size_t off = (size_t)r * DHID + c;
        float v = (g_acc[off] + g_hs[off]) * g_dis[r];
        g_acc[off] = v;
        s += v; q += v * v;
    }
    atomicAdd(&g_colsum[c], s);
    atomicAdd(&g_colsq[c], q);
}

// ================= finalize with bias (layer 3) =================
__global__ void k_finalize_bias(const float* __restrict__ bias, int M) {
    int idx = blockIdx.x * blockDim.x + threadIdx.x;
    int n4 = M * (DHID / 4);
    if (idx >= n4) return;
    int r  = idx >> 7;
    int c4 = idx & 127;
    float4 a = ((const float4*)g_acc)[idx];
    float4 h = ((const float4*)g_hs)[idx];
    float s = g_dis[r];
    float4 b = ((const float4*)bias)[c4];
    ((float4*)g_acc)[idx] = make_float4((a.x + h.x) * s + b.x,
                                        (a.y + h.y) * s + b.y,
                                        (a.z + h.z) * s + b.z,
                                        (a.w + h.w) * s + b.w);
}

// ================= BN apply + ReLU -> x_sel (fp32) + Ahi/Alo =================
__global__ void k_bn_apply(const float* __restrict__ gam, const float* __restrict__ bet,
                           int selOut, int M) {
    float* out = (selOut == 1) ? g_x1 : g_x2;
    int idx = blockIdx.x * blockDim.x + threadIdx.x;
    int n4 = M * (DHID / 4);
    if (idx >= n4) return;
    int c4 = idx & 127;
    float invN = 1.0f / (float)M;
    float4 v  = ((const float4*)g_acc)[idx];
    float4 s4 = ((const float4*)g_colsum)[c4];
    float4 q4 = ((const float4*)g_colsq)[c4];
    float4 gm = ((const float4*)gam)[c4];
    float4 bt = ((const float4*)bet)[c4];
    float4 o;
    { float mu = s4.x * invN; float var = q4.x * invN - mu * mu;
      o.x = fmaxf(0.f, (v.x - mu) * rsqrtf(var + 1e-5f) * gm.x + bt.x); }
    { float mu = s4.y * invN; float var = q4.y * invN - mu * mu;
      o.y = fmaxf(0.f, (v.y - mu) * rsqrtf(var + 1e-5f) * gm.y + bt.y); }
    { float mu = s4.z * invN; float var = q4.z * invN - mu * mu;
      o.z = fmaxf(0.f, (v.z - mu) * rsqrtf(var + 1e-5f) * gm.z + bt.z); }
    { float mu = s4.w * invN; float var = q4.w * invN - mu * mu;
      o.w = fmaxf(0.f, (v.w - mu) * rsqrtf(var + 1e-5f) * gm.w + bt.w); }
    ((float4*)out)[idx] = o;
    float hx = __bfloat162float(__float2bfloat16_rn(o.x));
    float hy = __bfloat162float(__float2bfloat16_rn(o.y));
    float hz = __bfloat162float(__float2bfloat16_rn(o.z));
    float hw = __bfloat162float(__float2bfloat16_rn(o.w));
    ((__nv_bfloat162*)g_Ahi)[idx * 2    ] = __floats2bfloat162_rn(o.x, o.y);
    ((__nv_bfloat162*)g_Ahi)[idx * 2 + 1] = __floats2bfloat162_rn(o.z, o.w);
    ((__nv_bfloat162*)g_Alo)[idx * 2    ] = __floats2bfloat162_rn(o.x - hx, o.y - hy);
    ((__nv_bfloat162*)g_Alo)[idx * 2 + 1] = __floats2bfloat162_rn(o.z - hz, o.w - hw);
}

// ================= JK max + classifier + log_softmax =================
__global__ void k_jk_head(const float* __restrict__ Wf, const float* __restrict__ bfv,
                          float* __restrict__ out) {
    __shared__ float h[DHID];
    __shared__ float logits[DOUT];
    __shared__ float red2[2];
    int r = blockIdx.x;
    size_t base = (size_t)r * DHID;
    for (int k = threadIdx.x; k < DHID; k += blockDim.x) {
        float v = fmaxf(g_x1[base + k], g_x2[base + k]);
        h[k] = fmaxf(v, g_acc[base + k]);
    }
    __syncthreads();
    int j = threadIdx.x;
    if (j < DOUT) {
        float a = bfv[j];
#pragma unroll 8
        for (int k = 0; k < DHID; k++) a += h[k] * Wf[k * DOUT + j];
        logits[j] = a;
    }
    __syncthreads();
    if (threadIdx.x == 0) {
        float m = -1e30f;
        for (int t = 0; t < DOUT; t++) m = fmaxf(m, logits[t]);
        float s = 0.f;
        for (int t = 0; t < DOUT; t++) s += expf(logits[t] - m);
        red2[0] = m; red2[1] = logf(s);
    }
    __syncthreads();
    if (j < DOUT) out[(size_t)r * DOUT + j] = logits[j] - red2[0] - red2[1];
}

// ================= host driver =================
extern "C" void kernel_launch(void* const* d_in, const int* in_sizes, int n_in,
                              void* d_out, int out_size) {
    const float* x   = (const float*)d_in[0];
    const int*   ei  = (const int*)  d_in[1];
    const float* W1  = (const float*)d_in[2];
    const float* g1  = (const float*)d_in[4];
    const float* be1 = (const float*)d_in[5];
    const float* W2  = (const float*)d_in[6];
    const float* g2  = (const float*)d_in[8];
    const float* be2 = (const float*)d_in[9];
    const float* W3  = (const float*)d_in[10];
    const float* b3  = (const float*)d_in[11];
    const float* Wf  = (const float*)d_in[12];
    const float* bf  = (const float*)d_in[13];
    float* out = (float*)d_out;

    int M = in_sizes[0] / DHID;     // 50000
    int E = in_sizes[1] / 2;        // 800000
    const int* src = ei;
    const int* dst = ei + E;

    int n4 = M * (DHID / 4);
    dim3 gemm_grid(DHID / 128, (M + 127) / 128);
    int statBlocks = (M + 127) / 128;

    // conversions
    k_convert_W<<<dim3(16, 16, 3), dim3(32, 32)>>>(W1, W2, W3);
    k_convert_x<<<(n4 + 255) / 256, 256>>>(x, M);

    // normalization coefficients
    k_init_deg   <<<(M + 255) / 256, 256>>>(M);
    k_deg_scatter<<<(E + 255) / 256, 256>>>(dst, E);
    k_deg_rsqrt  <<<(M + 255) / 256, 256>>>(M);

    // ---- layer 1 ----
    k_gemm_mma    <<<gemm_grid, 256>>>(0, M);
    k_zero_acc    <<<(n4 + 255) / 256, 256>>>(n4);
    k_edge_scatter<<<((size_t)E * 32 + 255) / 256, 256>>>(src, dst, E);
    k_zero_stats  <<<1, DHID>>>();
    k_fin_stats   <<<statBlocks, DHID>>>(M);       // bias cancels under BN
    k_bn_apply    <<<(n4 + 255) / 256, 256>>>(g1, be1, 1, M);

    // ---- layer 2 ----
    k_gemm_mma    <<<gemm_grid, 256>>>(1, M);
    k_zero_acc    <<<(n4 + 255) / 256, 256>>>(n4);
    k_edge_scatter<<<((size_t)E * 32 + 255) / 256, 256>>>(src, dst, E);
    k_zero_stats  <<<1, DHID>>>();
    k_fin_stats   <<<statBlocks, DHID>>>(M);
    k_bn_apply    <<<(n4 + 255) / 256, 256>>>(g2, be2, 2, M);

    // ---- layer 3 (no BN; x3 stays in g_acc) ----
    k_gemm_mma    <<<gemm_grid, 256>>>(2, M);
    k_zero_acc    <<<(n4 + 255) / 256, 256>>>(n4);
    k_edge_scatter<<<((size_t)E * 32 + 255) / 256, 256>>>(src, dst, E);
    k_finalize_bias<<<(n4 + 255) / 256, 256>>>(b3, M);

    // ---- JK max + classifier + log_softmax ----
    k_jk_head<<<M, 64>>>(Wf, bf, out);
}